// round 1
// baseline (speedup 1.0000x reference)
#include <cuda_runtime.h>
#include <math.h>

// ---------------- problem constants ----------------
#define NB 5
#define BATCH 512
#define KQ 64          // seq len per band
#define D 200
#define HEADS 4
#define HD 50
#define TKV 320        // NB*KQ
#define HID 512
#define FIN 64000      // NB*KQ*D
#define BAND_STRIDE 6553600ull   // BATCH*KQ*D
#define ROW_STRIDE 12800         // KQ*D
#define NSPLIT 8

// ---------------- scratch (__device__ globals; no allocs allowed) ----------------
__device__ float g_hpart[(size_t)NSPLIT * BATCH * HID];           // 8 MB
__device__ int   g_sel[BATCH];
__device__ float g_q [(size_t)BATCH * KQ * D];                    // 26 MB
__device__ float g_k [(size_t)BATCH * TKV * D];                   // 131 MB
__device__ float g_v [(size_t)BATCH * TKV * D];                   // 131 MB
__device__ float g_ao[(size_t)BATCH * KQ * D];                    // 26 MB

// =====================================================================
// Kernel 1: router GEMM, split-K.  hpart[s][b][j] = sum_{f in split s} flat[b,f]*w1[j,f]
// flat[b, n*12800 + r] = bands[n*BAND_STRIDE + b*12800 + r]  (contiguous per band)
// 64x64 tile, 4x4 microtile, kc=32, k-major smem.
// =====================================================================
__global__ __launch_bounds__(256) void router_gemm(const float* __restrict__ bands,
                                                   const float* __restrict__ w1)
{
    __shared__ float As[32][68];
    __shared__ float Ws[32][68];
    const int jt = blockIdx.x, bt = blockIdx.y, sp = blockIdx.z;
    const int tid = threadIdx.x;
    const int tx = tid & 15, ty = tid >> 4;
    const int b0 = bt * 64, j0 = jt * 64;
    const int rowA = tid >> 3;          // 0..31
    const int c4   = (tid & 7) << 2;    // 0,4,...,28

    float acc[4][4];
#pragma unroll
    for (int i = 0; i < 4; i++)
#pragma unroll
        for (int j = 0; j < 4; j++) acc[i][j] = 0.f;

    const int fBeg = sp * (FIN / NSPLIT);
    const int fEnd = fBeg + (FIN / NSPLIT);
    for (int f0 = fBeg; f0 < fEnd; f0 += 32) {
        // chunk [f0, f0+32) lies entirely within one band (12800 % 32 == 0)
        const int n = f0 / ROW_STRIDE;
        const int r = f0 - n * ROW_STRIDE;
        const float* Ab = bands + (size_t)n * BAND_STRIDE + (size_t)b0 * ROW_STRIDE + r;
        const float* Wb = w1 + (size_t)j0 * FIN + f0;
#pragma unroll
        for (int rr = 0; rr < 64; rr += 32) {
            const int rw = rowA + rr;
            float4 va = *(const float4*)(Ab + (size_t)rw * ROW_STRIDE + c4);
            As[c4 + 0][rw] = va.x; As[c4 + 1][rw] = va.y;
            As[c4 + 2][rw] = va.z; As[c4 + 3][rw] = va.w;
            float4 vw = *(const float4*)(Wb + (size_t)rw * FIN + c4);
            Ws[c4 + 0][rw] = vw.x; Ws[c4 + 1][rw] = vw.y;
            Ws[c4 + 2][rw] = vw.z; Ws[c4 + 3][rw] = vw.w;
        }
        __syncthreads();
#pragma unroll
        for (int k = 0; k < 32; k++) {
            float4 a = *(const float4*)&As[k][ty * 4];
            float4 w = *(const float4*)&Ws[k][tx * 4];
            float av[4] = {a.x, a.y, a.z, a.w};
            float wv[4] = {w.x, w.y, w.z, w.w};
#pragma unroll
            for (int i = 0; i < 4; i++)
#pragma unroll
                for (int j = 0; j < 4; j++) acc[i][j] += av[i] * wv[j];
        }
        __syncthreads();
    }
    float* outp = g_hpart + (size_t)sp * (BATCH * HID);
#pragma unroll
    for (int i = 0; i < 4; i++)
#pragma unroll
        for (int j = 0; j < 4; j++)
            outp[(size_t)(b0 + ty * 4 + i) * HID + (j0 + tx * 4 + j)] = acc[i][j];
}

// =====================================================================
// Kernel 2: sum split partials + bias + relu, logits = h @ w2^T + b2, argmax -> g_sel
// (softmax is monotone -> argmax of logits suffices)
// =====================================================================
__global__ __launch_bounds__(128) void router_select(const float* __restrict__ b1,
                                                     const float* __restrict__ w2,
                                                     const float* __restrict__ b2)
{
    const int b = blockIdx.x, tid = threadIdx.x;
    float acc[NB] = {0.f, 0.f, 0.f, 0.f, 0.f};
    for (int j = tid; j < HID; j += 128) {
        float hv = b1[j];
#pragma unroll
        for (int s = 0; s < NSPLIT; s++)
            hv += g_hpart[(size_t)s * BATCH * HID + (size_t)b * HID + j];
        hv = fmaxf(hv, 0.f);
#pragma unroll
        for (int n = 0; n < NB; n++) acc[n] += hv * w2[n * HID + j];
    }
    __shared__ float red[NB][128];
#pragma unroll
    for (int n = 0; n < NB; n++) red[n][tid] = acc[n];
    __syncthreads();
    for (int s = 64; s > 0; s >>= 1) {
        if (tid < s) {
#pragma unroll
            for (int n = 0; n < NB; n++) red[n][tid] += red[n][tid + s];
        }
        __syncthreads();
    }
    if (tid == 0) {
        int best = 0;
        float bv = red[0][0] + b2[0];
        for (int n = 1; n < NB; n++) {
            float v = red[n][0] + b2[n];
            if (v > bv) { bv = v; best = n; }
        }
        g_sel[b] = best;
    }
}

// =====================================================================
// Kernel 3/4/6: generic projection GEMM  out[64rows x N] = A[64x200] @ W[Nx200]^T + bias
//   MODE 0: Q proj     (A = bands[sel[b], b], N=200 -> g_q)
//   MODE 1: K/V proj   (A = bands[n, b],      N=400 -> g_k | g_v)
//   MODE 2: out proj   (A = g_ao tile,        N=200 -> d_out)
// 64x64 tile (N-bounds-checked), kc=50, k-major smem.
// =====================================================================
template <int MODE>
__global__ __launch_bounds__(256) void proj_gemm(const float* __restrict__ bands,
                                                 const float* __restrict__ W,
                                                 const float* __restrict__ bias,
                                                 float* __restrict__ outp)
{
    __shared__ float As[50][68];
    __shared__ float Ws[50][68];
    const int nt = blockIdx.x, mt = blockIdx.y;
    const int N = (MODE == 1) ? 400 : 200;

    const float* Ab;
    if (MODE == 0) {
        Ab = bands + (size_t)g_sel[mt] * BAND_STRIDE + (size_t)mt * ROW_STRIDE;
    } else if (MODE == 1) {
        const int b = mt / NB, n = mt % NB;
        Ab = bands + (size_t)n * BAND_STRIDE + (size_t)b * ROW_STRIDE;
    } else {
        Ab = g_ao + (size_t)mt * ROW_STRIDE;
    }

    const int j0 = nt * 64;
    const int tid = threadIdx.x, tx = tid & 15, ty = tid >> 4;
    float acc[4][4];
#pragma unroll
    for (int i = 0; i < 4; i++)
#pragma unroll
        for (int j = 0; j < 4; j++) acc[i][j] = 0.f;

    for (int ck = 0; ck < 200; ck += 50) {
        for (int idx = tid; idx < 64 * 50; idx += 256) {
            int row = idx / 50, col = idx - row * 50;
            As[col][row] = Ab[row * 200 + ck + col];
        }
        for (int idx = tid; idx < 64 * 50; idx += 256) {
            int row = idx / 50, col = idx - row * 50;
            int j = j0 + row;
            Ws[col][row] = (j < N) ? W[(size_t)j * 200 + ck + col] : 0.f;
        }
        __syncthreads();
#pragma unroll
        for (int k = 0; k < 50; k++) {
            float4 a = *(const float4*)&As[k][ty * 4];
            float4 w = *(const float4*)&Ws[k][tx * 4];
            float av[4] = {a.x, a.y, a.z, a.w};
            float wv[4] = {w.x, w.y, w.z, w.w};
#pragma unroll
            for (int i = 0; i < 4; i++)
#pragma unroll
                for (int j = 0; j < 4; j++) acc[i][j] += av[i] * wv[j];
        }
        __syncthreads();
    }

#pragma unroll
    for (int i = 0; i < 4; i++) {
        const int row = ty * 4 + i;
#pragma unroll
        for (int j = 0; j < 4; j++) {
            const int col = j0 + tx * 4 + j;
            if (col >= N) continue;
            float v = acc[i][j] + bias[col];
            if (MODE == 0) {
                g_q[((size_t)mt * 64 + row) * 200 + col] = v;
            } else if (MODE == 1) {
                const int b = mt / NB, n = mt % NB;
                const size_t t = (size_t)b * TKV + n * 64 + row;
                if (col < 200) g_k[t * 200 + col] = v;
                else           g_v[t * 200 + (col - 200)] = v;
            } else {
                outp[((size_t)mt * 64 + row) * 200 + col] = v;
            }
        }
    }
}

// =====================================================================
// Kernel 5: attention per (b, h). Scores 64x320 in smem, full softmax, O = P @ V.
// =====================================================================
#define ATTN_SMEM_FLOATS (3400 + 3400 + 64 * 321)
__global__ __launch_bounds__(256) void attn_kernel()
{
    extern __shared__ float sm[];
    float* sQ  = sm;              // [50][68] d-major
    float* sKV = sm + 3400;       // K: [50][68] d-major | V: [64][52] t-major
    float* sS  = sm + 6800;       // [64][321]

    const int h = blockIdx.x, b = blockIdx.y;
    const int tid = threadIdx.x, tx = tid & 15, ty = tid >> 4;

    const float* qb = g_q + (size_t)b * 64 * 200 + h * HD;
    for (int idx = tid; idx < 64 * 50; idx += 256) {
        int row = idx / 50, d = idx - row * 50;
        sQ[d * 68 + row] = qb[row * 200 + d];
    }

    const float scale = 0.14142135623730951f;  // 1/sqrt(50)
    for (int c = 0; c < 5; c++) {
        __syncthreads();   // previous chunk compute done (and Q load on c=0)
        const float* kb = g_k + ((size_t)b * TKV + c * 64) * 200 + h * HD;
        for (int idx = tid; idx < 64 * 50; idx += 256) {
            int row = idx / 50, d = idx - row * 50;
            sKV[d * 68 + row] = kb[row * 200 + d];
        }
        __syncthreads();
        float acc[4][4];
#pragma unroll
        for (int i = 0; i < 4; i++)
#pragma unroll
            for (int j = 0; j < 4; j++) acc[i][j] = 0.f;
#pragma unroll
        for (int k = 0; k < 50; k++) {
            float4 a = *(const float4*)&sQ[k * 68 + ty * 4];
            float4 kk = *(const float4*)&sKV[k * 68 + tx * 4];
            float av[4] = {a.x, a.y, a.z, a.w};
            float kv[4] = {kk.x, kk.y, kk.z, kk.w};
#pragma unroll
            for (int i = 0; i < 4; i++)
#pragma unroll
                for (int j = 0; j < 4; j++) acc[i][j] += av[i] * kv[j];
        }
#pragma unroll
        for (int i = 0; i < 4; i++)
#pragma unroll
            for (int j = 0; j < 4; j++)
                sS[(ty * 4 + i) * 321 + c * 64 + tx * 4 + j] = acc[i][j] * scale;
    }
    __syncthreads();

    // softmax: one warp per row, 8 rows per warp
    const int warp = tid >> 5, lane = tid & 31;
    for (int r = warp; r < 64; r += 8) {
        float* row = sS + (size_t)r * 321;
        float m = -1e30f;
        for (int t = lane; t < 320; t += 32) m = fmaxf(m, row[t]);
#pragma unroll
        for (int o = 16; o; o >>= 1) m = fmaxf(m, __shfl_xor_sync(0xffffffffu, m, o));
        float s = 0.f;
        for (int t = lane; t < 320; t += 32) { float e = __expf(row[t] - m); row[t] = e; s += e; }
#pragma unroll
        for (int o = 16; o; o >>= 1) s += __shfl_xor_sync(0xffffffffu, s, o);
        const float inv = 1.f / s;
        for (int t = lane; t < 320; t += 32) row[t] *= inv;
    }
    __syncthreads();

    // O = P @ V
    float oa[4][4];
#pragma unroll
    for (int i = 0; i < 4; i++)
#pragma unroll
        for (int j = 0; j < 4; j++) oa[i][j] = 0.f;

    for (int c = 0; c < 5; c++) {
        const float* vb = g_v + ((size_t)b * TKV + c * 64) * 200 + h * HD;
        for (int idx = tid; idx < 64 * 50; idx += 256) {
            int t = idx / 50, d = idx - t * 50;
            sKV[t * 52 + d] = vb[t * 200 + d];
        }
        __syncthreads();
        if (tx < 13) {
#pragma unroll 8
            for (int t = 0; t < 64; t++) {
                float4 v4 = *(const float4*)&sKV[t * 52 + tx * 4];
#pragma unroll
                for (int i = 0; i < 4; i++) {
                    float a = sS[(ty * 4 + i) * 321 + c * 64 + t];
                    oa[i][0] += a * v4.x; oa[i][1] += a * v4.y;
                    oa[i][2] += a * v4.z; oa[i][3] += a * v4.w;
                }
            }
        }
        __syncthreads();
    }

    if (tx < 13) {
#pragma unroll
        for (int i = 0; i < 4; i++) {
            const int row = ty * 4 + i;
#pragma unroll
            for (int j = 0; j < 4; j++) {
                const int col = tx * 4 + j;
                if (col < HD)
                    g_ao[((size_t)b * 64 + row) * 200 + h * HD + col] = oa[i][j];
            }
        }
    }
}

// =====================================================================
// launch
// =====================================================================
extern "C" void kernel_launch(void* const* d_in, const int* in_sizes, int n_in,
                              void* d_out, int out_size)
{
    const float* bands = (const float*)d_in[0];
    const float* w1    = (const float*)d_in[1];
    const float* b1    = (const float*)d_in[2];
    const float* w2    = (const float*)d_in[3];
    const float* b2    = (const float*)d_in[4];
    const float* ipw   = (const float*)d_in[5];
    const float* ipb   = (const float*)d_in[6];
    const float* ow    = (const float*)d_in[7];
    const float* ob    = (const float*)d_in[8];
    float* outp = (float*)d_out;

    const int attn_smem = ATTN_SMEM_FLOATS * (int)sizeof(float);  // 109,376 B
    cudaFuncSetAttribute(attn_kernel, cudaFuncAttributeMaxDynamicSharedMemorySize, attn_smem);

    router_gemm  <<<dim3(8, 8, NSPLIT), 256>>>(bands, w1);
    router_select<<<BATCH, 128>>>(b1, w2, b2);
    proj_gemm<0> <<<dim3(4, BATCH), 256>>>(bands, ipw, ipb, nullptr);            // Q
    proj_gemm<1> <<<dim3(7, BATCH * NB), 256>>>(bands, ipw + 200 * 200, ipb + 200, nullptr); // K,V
    attn_kernel  <<<dim3(HEADS, BATCH), 256, attn_smem>>>();
    proj_gemm<2> <<<dim3(4, BATCH), 256>>>(bands, ow, ob, outp);                 // out proj
}

// round 4
// speedup vs baseline: 2.1017x; 2.1017x over previous
#include <cuda_runtime.h>
#include <cuda_fp16.h>
#include <cstdint>
#include <math.h>

// ---------------- problem constants ----------------
#define NB 5
#define BATCH 512
#define KQ 64
#define D 200
#define HEADS 4
#define HD 50
#define TKV 320
#define HID 512
#define FIN 64000
#define BAND_STRIDE 6553600ull   // BATCH*KQ*D (elements)
#define ROW_STRIDE 12800         // KQ*D
#define R_NSPLIT 9

// ---------------- scratch ----------------
__device__ float  g_hpart[(size_t)R_NSPLIT * BATCH * HID];
__device__ int    g_sel[BATCH];
__device__ float  g_q [(size_t)BATCH * KQ * D];
__device__ float  g_k [(size_t)BATCH * TKV * D];
__device__ float  g_v [(size_t)BATCH * TKV * D];
__device__ float  g_ao[(size_t)BATCH * KQ * D];
__device__ __half g_bh [(size_t)NB * BAND_STRIDE];   // bands * 4, hi
__device__ __half g_bl [(size_t)NB * BAND_STRIDE];   // bands * 4, lo
__device__ __half g_w1h[(size_t)HID * FIN];          // w1 * 256, hi
__device__ __half g_w1l[(size_t)HID * FIN];          // w1 * 256, lo
__device__ __half g_wkvh[448 * 256];                 // wk|wv * 256 padded, hi
__device__ __half g_wkvl[448 * 256];                 // lo

// =====================================================================
// helpers: mma.sync / ldmatrix / cp.async (all legal on plain sm_103)
// =====================================================================
__device__ __forceinline__ uint32_t smem_u32(const void* p) {
    uint32_t a;
    asm("{ .reg .u64 t; cvta.to.shared.u64 t, %1; cvt.u32.u64 %0, t; }" : "=r"(a) : "l"(p));
    return a;
}
__device__ __forceinline__ void cp16(uint32_t dst, const void* src) {
    asm volatile("cp.async.cg.shared.global [%0], [%1], 16;" :: "r"(dst), "l"(src));
}
#define CP_COMMIT() asm volatile("cp.async.commit_group;" ::: "memory")
#define CP_WAIT1()  asm volatile("cp.async.wait_group 1;" ::: "memory")
#define CP_WAIT0()  asm volatile("cp.async.wait_group 0;" ::: "memory")

__device__ __forceinline__ void ldsm4(uint32_t* r, uint32_t a) {
    asm volatile("ldmatrix.sync.aligned.m8n8.x4.shared.b16 {%0,%1,%2,%3}, [%4];"
        : "=r"(r[0]), "=r"(r[1]), "=r"(r[2]), "=r"(r[3]) : "r"(a));
}
__device__ __forceinline__ void ldsm2(uint32_t* r, uint32_t a) {
    asm volatile("ldmatrix.sync.aligned.m8n8.x2.shared.b16 {%0,%1}, [%2];"
        : "=r"(r[0]), "=r"(r[1]) : "r"(a));
}
__device__ __forceinline__ void mma16816(float* c, const uint32_t* a, const uint32_t* b) {
    asm volatile("mma.sync.aligned.m16n8k16.row.col.f32.f16.f16.f32 "
        "{%0,%1,%2,%3}, {%4,%5,%6,%7}, {%8,%9}, {%0,%1,%2,%3};"
        : "+f"(c[0]), "+f"(c[1]), "+f"(c[2]), "+f"(c[3])
        : "r"(a[0]), "r"(a[1]), "r"(a[2]), "r"(a[3]), "r"(b[0]), "r"(b[1]));
}

// =====================================================================
// Conversion kernels: fp32 -> scaled fp16 hi/lo split
// =====================================================================
__global__ __launch_bounds__(256) void conv_split(const float* __restrict__ src,
                                                  __half* __restrict__ dh,
                                                  __half* __restrict__ dl,
                                                  int n4, float s)
{
    int i = blockIdx.x * blockDim.x + threadIdx.x;
    if (i >= n4) return;
    float4 v = ((const float4*)src)[i];
    float x0 = v.x * s, x1 = v.y * s, x2 = v.z * s, x3 = v.w * s;
    __half h0 = __float2half_rn(x0), h1 = __float2half_rn(x1);
    __half h2 = __float2half_rn(x2), h3 = __float2half_rn(x3);
    __half l0 = __float2half_rn(x0 - __half2float(h0));
    __half l1 = __float2half_rn(x1 - __half2float(h1));
    __half l2 = __float2half_rn(x2 - __half2float(h2));
    __half l3 = __float2half_rn(x3 - __half2float(h3));
    ((__half2*)dh)[2 * i]     = __halves2half2(h0, h1);
    ((__half2*)dh)[2 * i + 1] = __halves2half2(h2, h3);
    ((__half2*)dl)[2 * i]     = __halves2half2(l0, l1);
    ((__half2*)dl)[2 * i + 1] = __halves2half2(l2, l3);
}

__global__ __launch_bounds__(256) void conv_wkv_k(const float* __restrict__ ipw)
{
    const int row = blockIdx.x;        // 0..447 (0..199 = wk, 200..399 = wv, pad)
    const int col = threadIdx.x;       // 0..255
    float v = 0.f;
    if (row < 400 && col < 200) v = ipw[(size_t)(200 + row) * 200 + col] * 256.f;
    __half h = __float2half_rn(v);
    __half l = __float2half_rn(v - __half2float(h));
    g_wkvh[row * 256 + col] = h;
    g_wkvl[row * 256 + col] = l;
}

// =====================================================================
// Router GEMM: hpart[sp][b][j] = sum_f flat[b,f] w1[j,f]  (fp16 3-term HMMA)
// CTA: M=128(batch) x N=128(hid), kc=64, split-K over sp.
// smem stage p (64KB): Ah@0, Al@16K, Bh@32K, Bl@48K; two stages = 128KB
// =====================================================================
#define R_SMEM (2 * 65536)
__global__ __launch_bounds__(256) void router_mma(void)
{
    extern __shared__ char smc[];
    const uint32_t sb = smem_u32(smc);
    const int tid = threadIdx.x, lane = tid & 31, wid = tid >> 5;
    const int jt = blockIdx.x, mt = blockIdx.y, sp = blockIdx.z;
    const int b0 = mt * 128, j0 = jt * 128;
    const int wm = wid & 1, wn = wid >> 1;           // 2 x 4 warp grid
    const int m_base = wm * 64, n_base = wn * 32;

    // ldmatrix lane geometry
    const int a_row  = (lane & 7) + ((lane >> 3) & 1) * 8;
    const int a_koff = (lane >> 4) * 16;
    const int bl_    = lane & 15;
    const int b_row  = bl_ & 7;
    const int b_koff = (bl_ >> 3) * 16;
    int rowbyteA[4], rowbyteB[4];
#pragma unroll
    for (int mi = 0; mi < 4; mi++) rowbyteA[mi] = (m_base + mi * 16 + a_row) * 128;
#pragma unroll
    for (int ni = 0; ni < 4; ni++) rowbyteB[ni] = (n_base + ni * 8 + b_row) * 128;
    const int swzA = (lane & 7) << 4;
    const int swzB = b_row << 4;

    float C[4][4][4];
#pragma unroll
    for (int a = 0; a < 4; a++)
#pragma unroll
        for (int b = 0; b < 4; b++)
#pragma unroll
            for (int c = 0; c < 4; c++) C[a][b][c] = 0.f;

    const int cbeg = sp * 111 + (sp > 0 ? 1 : 0);
    const int cnt  = 111 + (sp == 0 ? 1 : 0);

    auto issue_chunk = [&](int c, int p) {
        const int n = c / 200;
        const int rr = (c - n * 200) * 64;
        const __half* Ah = g_bh + (size_t)n * BAND_STRIDE + (size_t)b0 * ROW_STRIDE + rr;
        const __half* Al = g_bl + (size_t)n * BAND_STRIDE + (size_t)b0 * ROW_STRIDE + rr;
        const size_t f0 = (size_t)c * 64;
        const uint32_t so = sb + p * 65536;
#pragma unroll
        for (int j = 0; j < 4; j++) {
            const int u = tid + j * 256;          // 0..1023
            const int row = u >> 3, uu = u & 7;
            const uint32_t d = row * 128 + ((uu * 16) ^ ((row & 7) << 4));
            cp16(so + d,         Ah + (size_t)row * ROW_STRIDE + uu * 8);
            cp16(so + 16384 + d, Al + (size_t)row * ROW_STRIDE + uu * 8);
            const __half* Bh = g_w1h + (size_t)(j0 + row) * FIN + f0 + uu * 8;
            const __half* Bl = g_w1l + (size_t)(j0 + row) * FIN + f0 + uu * 8;
            cp16(so + 32768 + d, Bh);
            cp16(so + 49152 + d, Bl);
        }
    };

    issue_chunk(cbeg, 0);
    CP_COMMIT();

    for (int c = 0; c < cnt; c++) {
        const int p = c & 1;
        if (c + 1 < cnt) { issue_chunk(cbeg + c + 1, p ^ 1); CP_COMMIT(); CP_WAIT1(); }
        else             { CP_WAIT0(); }
        __syncthreads();
        const uint32_t so = sb + p * 65536;
#pragma unroll
        for (int ks = 0; ks < 4; ks++) {
            uint32_t bhf[4][2], blf[4][2];
#pragma unroll
            for (int ni = 0; ni < 4; ni++) {
                const uint32_t ad = so + 32768 + rowbyteB[ni] + ((ks * 32 + b_koff) ^ swzB);
                ldsm2(bhf[ni], ad);
                ldsm2(blf[ni], ad + 16384);
            }
#pragma unroll
            for (int mi = 0; mi < 4; mi++) {
                uint32_t ah[4], al[4];
                const uint32_t aa = so + rowbyteA[mi] + ((ks * 32 + a_koff) ^ swzA);
                ldsm4(ah, aa);
                ldsm4(al, aa + 16384);
#pragma unroll
                for (int ni = 0; ni < 4; ni++) {
                    mma16816(C[mi][ni], ah, bhf[ni]);
                    mma16816(C[mi][ni], ah, blf[ni]);
                    mma16816(C[mi][ni], al, bhf[ni]);
                }
            }
        }
        __syncthreads();
    }

    const float invS = 1.f / 1024.f;
    float* outp = g_hpart + (size_t)sp * (BATCH * HID);
    const int g = lane >> 2, qp = lane & 3;
#pragma unroll
    for (int mi = 0; mi < 4; mi++) {
#pragma unroll
        for (int ni = 0; ni < 4; ni++) {
            const int row = b0 + m_base + mi * 16 + g;
            const int col = j0 + n_base + ni * 8 + qp * 2;
            *(float2*)(outp + (size_t)row * HID + col) =
                make_float2(C[mi][ni][0] * invS, C[mi][ni][1] * invS);
            *(float2*)(outp + (size_t)(row + 8) * HID + col) =
                make_float2(C[mi][ni][2] * invS, C[mi][ni][3] * invS);
        }
    }
}

// =====================================================================
// Router select: reduce partials + relu, logits, argmax -> g_sel
// =====================================================================
__global__ __launch_bounds__(128) void router_select(const float* __restrict__ b1,
                                                     const float* __restrict__ w2,
                                                     const float* __restrict__ b2)
{
    const int b = blockIdx.x, tid = threadIdx.x;
    float acc[NB] = {0.f, 0.f, 0.f, 0.f, 0.f};
    for (int j = tid; j < HID; j += 128) {
        float hv = b1[j];
#pragma unroll
        for (int s = 0; s < R_NSPLIT; s++)
            hv += g_hpart[(size_t)s * BATCH * HID + (size_t)b * HID + j];
        hv = fmaxf(hv, 0.f);
#pragma unroll
        for (int n = 0; n < NB; n++) acc[n] += hv * w2[n * HID + j];
    }
    __shared__ float red[NB][128];
#pragma unroll
    for (int n = 0; n < NB; n++) red[n][tid] = acc[n];
    __syncthreads();
    for (int s = 64; s > 0; s >>= 1) {
        if (tid < s) {
#pragma unroll
            for (int n = 0; n < NB; n++) red[n][tid] += red[n][tid + s];
        }
        __syncthreads();
    }
    if (tid == 0) {
        int best = 0;
        float bv = red[0][0] + b2[0];
        for (int n = 1; n < NB; n++) {
            float v = red[n][0] + b2[n];
            if (v > bv) { bv = v; best = n; }
        }
        g_sel[b] = best;
    }
}

// =====================================================================
// K/V projection: per (band n, batch-pair bp): A = 128 rows x K=200 resident,
// loop 7 n-tiles of 64 over padded wk|wv [448][256].
// smem: Ah@0(64K: 4 chunks x16K), Al@64K, Bh@128K(32K: 4 chunks x8K), Bl@160K,
// bias@192K (1600B). total 194*1024ish
// =====================================================================
#define KV_AH 0
#define KV_AL 65536
#define KV_BH 131072
#define KV_BL 163840
#define KV_BIAS 196608
#define KV_SMEM (196608 + 1664)
__global__ __launch_bounds__(256) void kv_mma(const float* __restrict__ ipb)
{
    extern __shared__ char smc[];
    const uint32_t sb = smem_u32(smc);
    const int tid = threadIdx.x, lane = tid & 31, wid = tid >> 5;
    const int n = blockIdx.x, bp = blockIdx.y;
    const int wm = wid & 1, wn = wid >> 1;           // 2(M) x 4(N)
    const int m_base = wm * 64;

    float* bias = (float*)(smc + KV_BIAS);
    for (int i = tid; i < 400; i += 256) bias[i] = ipb[200 + i];

    // zero the A chunk-3 pad units (uu 1..7)
#pragma unroll
    for (int j = 0; j < 4; j++) {
        const int u = tid + j * 256;
        if (u < 896) {
            const int row = u / 7, uu = 1 + (u % 7);
            const uint32_t d = 3 * 16384 + row * 128 + ((uu * 16) ^ ((row & 7) << 4));
            *(uint4*)(smc + KV_AH + d) = make_uint4(0, 0, 0, 0);
            *(uint4*)(smc + KV_AL + d) = make_uint4(0, 0, 0, 0);
        }
    }

    // async-load full A (128 rows x 25 real 16B units per array)
    {
        const size_t abase = (size_t)n * BAND_STRIDE + (size_t)(bp * 128) * 200;
#pragma unroll
        for (int j = 0; j < 13; j++) {
            const int u = tid + j * 256;
            if (u < 3200) {
                const int row = u / 25;
                const int rem = u - row * 25;
                const int ch = rem >> 3, uu = rem & 7;
                const uint32_t d = ch * 16384 + row * 128 + ((uu * 16) ^ ((row & 7) << 4));
                const size_t srow = abase + (size_t)row * 200 + ch * 64 + uu * 8;
                cp16(sb + KV_AH + d, g_bh + srow);
                cp16(sb + KV_AL + d, g_bl + srow);
            }
        }
        CP_COMMIT();
        CP_WAIT0();
    }
    __syncthreads();

    // ldmatrix lane geometry
    const int a_row  = (lane & 7) + ((lane >> 3) & 1) * 8;
    const int a_koff = (lane >> 4) * 16;
    const int bl_    = lane & 15;
    const int b_row  = bl_ & 7;
    const int b_koff = (bl_ >> 3) * 16;
    int rowbyteA[4], rowbyteB[2];
#pragma unroll
    for (int mi = 0; mi < 4; mi++) rowbyteA[mi] = (m_base + mi * 16 + a_row) * 128;
#pragma unroll
    for (int ni = 0; ni < 2; ni++) rowbyteB[ni] = (wn * 16 + ni * 8 + b_row) * 128;
    const int swzA = (lane & 7) << 4;
    const int swzB = b_row << 4;
    const int g = lane >> 2, qp = lane & 3;
    const float invS = 1.f / 1024.f;

    for (int nt = 0; nt < 7; nt++) {
        __syncthreads();   // previous compute done before overwriting B
        // load B tile [64 rows][256 cols] hi+lo (synchronous; padded source)
#pragma unroll
        for (int j = 0; j < 8; j++) {
            const int u = tid + j * 256;          // 0..2047
            const int lr = u >> 5;
            const int rem = u & 31;
            const int ch = rem >> 3, uu = rem & 7;
            const int nr = nt * 64 + lr;
            const uint4 vh = *(const uint4*)(g_wkvh + (size_t)nr * 256 + ch * 64 + uu * 8);
            const uint4 vl = *(const uint4*)(g_wkvl + (size_t)nr * 256 + ch * 64 + uu * 8);
            const uint32_t d = ch * 8192 + lr * 128 + ((uu * 16) ^ ((lr & 7) << 4));
            *(uint4*)(smc + KV_BH + d) = vh;
            *(uint4*)(smc + KV_BL + d) = vl;
        }
        __syncthreads();

        float C[4][2][4];
#pragma unroll
        for (int a = 0; a < 4; a++)
#pragma unroll
            for (int b = 0; b < 2; b++)
#pragma unroll
                for (int c = 0; c < 4; c++) C[a][b][c] = 0.f;

        for (int ks = 0; ks < 13; ks++) {
            const int ch = ks >> 2, ki = ks & 3;
            uint32_t bhf[2][2], blf[2][2];
#pragma unroll
            for (int ni = 0; ni < 2; ni++) {
                const uint32_t ad = sb + KV_BH + ch * 8192 + rowbyteB[ni] + ((ki * 32 + b_koff) ^ swzB);
                ldsm2(bhf[ni], ad);
                ldsm2(blf[ni], ad + 32768);
            }
#pragma unroll
            for (int mi = 0; mi < 4; mi++) {
                uint32_t ah[4], al[4];
                const uint32_t aa = sb + KV_AH + ch * 16384 + rowbyteA[mi] + ((ki * 32 + a_koff) ^ swzA);
                ldsm4(ah, aa);
                ldsm4(al, aa + 65536);
#pragma unroll
                for (int ni = 0; ni < 2; ni++) {
                    mma16816(C[mi][ni], ah, bhf[ni]);
                    mma16816(C[mi][ni], ah, blf[ni]);
                    mma16816(C[mi][ni], al, bhf[ni]);
                }
            }
        }

        // epilogue: scale + bias -> g_k / g_v
#pragma unroll
        for (int mi = 0; mi < 4; mi++) {
#pragma unroll
            for (int ni = 0; ni < 2; ni++) {
                const int col = nt * 64 + wn * 16 + ni * 8 + qp * 2;
                if (col >= 400) continue;
                const float bc0 = bias[col], bc1 = bias[col + 1];
#pragma unroll
                for (int half_ = 0; half_ < 2; half_++) {
                    const int r = m_base + mi * 16 + g + half_ * 8;
                    const int b = 2 * bp + (r >> 6);
                    const size_t t = (size_t)b * TKV + n * 64 + (r & 63);
                    const float v0 = C[mi][ni][half_ * 2 + 0] * invS + bc0;
                    const float v1 = C[mi][ni][half_ * 2 + 1] * invS + bc1;
                    float* dst = (col < 200) ? (g_k + t * 200 + col)
                                             : (g_v + t * 200 + (col - 200));
                    *(float2*)dst = make_float2(v0, v1);
                }
            }
        }
    }
}

// =====================================================================
// SIMT projection GEMM (Q proj MODE 0 + out proj MODE 2), from R1
// =====================================================================
template <int MODE>
__global__ __launch_bounds__(256) void proj_gemm(const float* __restrict__ bands,
                                                 const float* __restrict__ W,
                                                 const float* __restrict__ bias,
                                                 float* __restrict__ outp)
{
    __shared__ float As[50][68];
    __shared__ float Ws[50][68];
    const int nt = blockIdx.x, mt = blockIdx.y;
    const int N = 200;

    const float* Ab;
    if (MODE == 0) Ab = bands + (size_t)g_sel[mt] * BAND_STRIDE + (size_t)mt * ROW_STRIDE;
    else           Ab = g_ao + (size_t)mt * ROW_STRIDE;

    const int j0 = nt * 64;
    const int tid = threadIdx.x, tx = tid & 15, ty = tid >> 4;
    float acc[4][4];
#pragma unroll
    for (int i = 0; i < 4; i++)
#pragma unroll
        for (int j = 0; j < 4; j++) acc[i][j] = 0.f;

    for (int ck = 0; ck < 200; ck += 50) {
        for (int idx = tid; idx < 64 * 50; idx += 256) {
            int row = idx / 50, col = idx - row * 50;
            As[col][row] = Ab[row * 200 + ck + col];
        }
        for (int idx = tid; idx < 64 * 50; idx += 256) {
            int row = idx / 50, col = idx - row * 50;
            int j = j0 + row;
            Ws[col][row] = (j < N) ? W[(size_t)j * 200 + ck + col] : 0.f;
        }
        __syncthreads();
#pragma unroll
        for (int k = 0; k < 50; k++) {
            float4 a = *(const float4*)&As[k][ty * 4];
            float4 w = *(const float4*)&Ws[k][tx * 4];
            float av[4] = {a.x, a.y, a.z, a.w};
            float wv[4] = {w.x, w.y, w.z, w.w};
#pragma unroll
            for (int i = 0; i < 4; i++)
#pragma unroll
                for (int j = 0; j < 4; j++) acc[i][j] += av[i] * wv[j];
        }
        __syncthreads();
    }

#pragma unroll
    for (int i = 0; i < 4; i++) {
        const int row = ty * 4 + i;
#pragma unroll
        for (int j = 0; j < 4; j++) {
            const int col = j0 + tx * 4 + j;
            if (col >= N) continue;
            float v = acc[i][j] + bias[col];
            if (MODE == 0) g_q[((size_t)mt * 64 + row) * 200 + col] = v;
            else           outp[((size_t)mt * 64 + row) * 200 + col] = v;
        }
    }
}

// =====================================================================
// Attention per (b, h), from R1
// =====================================================================
#define ATTN_SMEM_FLOATS (3400 + 3400 + 64 * 321)
__global__ __launch_bounds__(256) void attn_kernel()
{
    extern __shared__ float smf[];
    float* sQ  = smf;
    float* sKV = smf + 3400;
    float* sS  = smf + 6800;

    const int h = blockIdx.x, b = blockIdx.y;
    const int tid = threadIdx.x, tx = tid & 15, ty = tid >> 4;

    const float* qb = g_q + (size_t)b * 64 * 200 + h * HD;
    for (int idx = tid; idx < 64 * 50; idx += 256) {
        int row = idx / 50, d = idx - row * 50;
        sQ[d * 68 + row] = qb[row * 200 + d];
    }

    const float scale = 0.14142135623730951f;
    for (int c = 0; c < 5; c++) {
        __syncthreads();
        const float* kb = g_k + ((size_t)b * TKV + c * 64) * 200 + h * HD;
        for (int idx = tid; idx < 64 * 50; idx += 256) {
            int row = idx / 50, d = idx - row * 50;
            sKV[d * 68 + row] = kb[row * 200 + d];
        }
        __syncthreads();
        float acc[4][4];
#pragma unroll
        for (int i = 0; i < 4; i++)
#pragma unroll
            for (int j = 0; j < 4; j++) acc[i][j] = 0.f;
#pragma unroll
        for (int k = 0; k < 50; k++) {
            float4 a = *(const float4*)&sQ[k * 68 + ty * 4];
            float4 kk = *(const float4*)&sKV[k * 68 + tx * 4];
            float av[4] = {a.x, a.y, a.z, a.w};
            float kv[4] = {kk.x, kk.y, kk.z, kk.w};
#pragma unroll
            for (int i = 0; i < 4; i++)
#pragma unroll
                for (int j = 0; j < 4; j++) acc[i][j] += av[i] * kv[j];
        }
#pragma unroll
        for (int i = 0; i < 4; i++)
#pragma unroll
            for (int j = 0; j < 4; j++)
                sS[(ty * 4 + i) * 321 + c * 64 + tx * 4 + j] = acc[i][j] * scale;
    }
    __syncthreads();

    const int warp = tid >> 5, lane = tid & 31;
    for (int r = warp; r < 64; r += 8) {
        float* row = sS + (size_t)r * 321;
        float m = -1e30f;
        for (int t = lane; t < 320; t += 32) m = fmaxf(m, row[t]);
#pragma unroll
        for (int o = 16; o; o >>= 1) m = fmaxf(m, __shfl_xor_sync(0xffffffffu, m, o));
        float s = 0.f;
        for (int t = lane; t < 320; t += 32) { float e = __expf(row[t] - m); row[t] = e; s += e; }
#pragma unroll
        for (int o = 16; o; o >>= 1) s += __shfl_xor_sync(0xffffffffu, s, o);
        const float inv = 1.f / s;
        for (int t = lane; t < 320; t += 32) row[t] *= inv;
    }
    __syncthreads();

    float oa[4][4];
#pragma unroll
    for (int i = 0; i < 4; i++)
#pragma unroll
        for (int j = 0; j < 4; j++) oa[i][j] = 0.f;

    for (int c = 0; c < 5; c++) {
        const float* vb = g_v + ((size_t)b * TKV + c * 64) * 200 + h * HD;
        for (int idx = tid; idx < 64 * 50; idx += 256) {
            int t = idx / 50, d = idx - t * 50;
            sKV[t * 52 + d] = vb[t * 200 + d];
        }
        __syncthreads();
        if (tx < 13) {
#pragma unroll 8
            for (int t = 0; t < 64; t++) {
                float4 v4 = *(const float4*)&sKV[t * 52 + tx * 4];
#pragma unroll
                for (int i = 0; i < 4; i++) {
                    float a = sS[(ty * 4 + i) * 321 + c * 64 + t];
                    oa[i][0] += a * v4.x; oa[i][1] += a * v4.y;
                    oa[i][2] += a * v4.z; oa[i][3] += a * v4.w;
                }
            }
        }
        __syncthreads();
    }

    if (tx < 13) {
#pragma unroll
        for (int i = 0; i < 4; i++) {
            const int row = ty * 4 + i;
#pragma unroll
            for (int j = 0; j < 4; j++) {
                const int col = tx * 4 + j;
                if (col < HD)
                    g_ao[((size_t)b * 64 + row) * 200 + h * HD + col] = oa[i][j];
            }
        }
    }
}

// =====================================================================
// launch
// =====================================================================
extern "C" void kernel_launch(void* const* d_in, const int* in_sizes, int n_in,
                              void* d_out, int out_size)
{
    const float* bands = (const float*)d_in[0];
    const float* w1    = (const float*)d_in[1];
    const float* b1    = (const float*)d_in[2];
    const float* w2    = (const float*)d_in[3];
    const float* b2    = (const float*)d_in[4];
    const float* ipw   = (const float*)d_in[5];
    const float* ipb   = (const float*)d_in[6];
    const float* ow    = (const float*)d_in[7];
    const float* ob    = (const float*)d_in[8];
    float* outp = (float*)d_out;

    const int attn_smem = ATTN_SMEM_FLOATS * (int)sizeof(float);
    cudaFuncSetAttribute(attn_kernel, cudaFuncAttributeMaxDynamicSharedMemorySize, attn_smem);
    cudaFuncSetAttribute(router_mma, cudaFuncAttributeMaxDynamicSharedMemorySize, R_SMEM);
    cudaFuncSetAttribute(kv_mma, cudaFuncAttributeMaxDynamicSharedMemorySize, KV_SMEM);

    __half *bh, *blp, *w1h, *w1l;
    cudaGetSymbolAddress((void**)&bh,  g_bh);
    cudaGetSymbolAddress((void**)&blp, g_bl);
    cudaGetSymbolAddress((void**)&w1h, g_w1h);
    cudaGetSymbolAddress((void**)&w1l, g_w1l);

    const int n4 = (NB * (int)BAND_STRIDE) / 4;      // 8,192,000 float4s (same for w1)
    conv_split<<<(n4 + 255) / 256, 256>>>(bands, bh,  blp, n4, 4.f);
    conv_split<<<(n4 + 255) / 256, 256>>>(w1,    w1h, w1l, n4, 256.f);
    conv_wkv_k<<<448, 256>>>(ipw);

    router_mma   <<<dim3(4, 4, R_NSPLIT), 256, R_SMEM>>>();
    router_select<<<BATCH, 128>>>(b1, w2, b2);
    proj_gemm<0> <<<dim3(4, BATCH), 256>>>(bands, ipw, ipb, nullptr);   // Q
    kv_mma       <<<dim3(NB, BATCH / 2), 256, KV_SMEM>>>(ipb);
    attn_kernel  <<<dim3(HEADS, BATCH), 256, attn_smem>>>();
    proj_gemm<2> <<<dim3(4, BATCH), 256>>>(bands, ow, ob, outp);        // out proj
}